// round 1
// baseline (speedup 1.0000x reference)
#include <cuda_runtime.h>
#include <cuda_bf16.h>

// Scratch for per-row partial MSE (no device allocation allowed -> __device__ global).
#define MAX_B 8192
__device__ float g_row_mse[MAX_B];

// ---------------------------------------------------------------------------
// Kernel 1: one block per row. Computes sum_{t<L} (pred[t] - log(align[t]))^2 / L.
// Reads ONLY the valid prefix of each row (ceil(L/4) float4 chunks) -> ~halves
// HBM traffic vs reading full rows, since E[L] ~ T/2.
// ---------------------------------------------------------------------------
template <int BLOCK>
__global__ void row_mse_kernel(const float* __restrict__ pred,
                               const float* __restrict__ align,
                               const int* __restrict__ lens,
                               int T) {
    const int row = blockIdx.x;
    const int L = lens[row];
    const size_t base = (size_t)row * (size_t)T;
    const float4* __restrict__ p4 = reinterpret_cast<const float4*>(pred + base);
    const float4* __restrict__ a4 = reinterpret_cast<const float4*>(align + base);

    const int nvec = (L + 3) >> 2;        // float4 chunks covering valid prefix
    const int nfull = L >> 2;             // chunks with all 4 lanes valid

    float acc = 0.0f;

    // Full chunks: branch-free hot path.
    for (int i = threadIdx.x; i < nfull; i += BLOCK) {
        float4 p = p4[i];
        float4 a = a4[i];
        float d0 = p.x - __logf(a.x);
        float d1 = p.y - __logf(a.y);
        float d2 = p.z - __logf(a.z);
        float d3 = p.w - __logf(a.w);
        acc = fmaf(d0, d0, acc);
        acc = fmaf(d1, d1, acc);
        acc = fmaf(d2, d2, acc);
        acc = fmaf(d3, d3, acc);
    }

    // At most one partial tail chunk (handled by the thread that owns it).
    if (nvec != nfull) {
        int i = nfull;
        if ((i % BLOCK) == (threadIdx.x % BLOCK) && (i / BLOCK) * BLOCK + threadIdx.x == i) {
            // simpler: only the thread with threadIdx.x == i % BLOCK in the right
            // stride iteration handles it; since i < nvec <= nfull+1 and the loop
            // above stops at nfull, just let threadIdx.x == (i % BLOCK) do it.
        }
        if (threadIdx.x == (nfull % BLOCK)) {
            float4 p = p4[i];
            float4 a = a4[i];
            int rem = L - (nfull << 2);   // 1..3 valid lanes
            float d;
            d = p.x - __logf(a.x); acc = fmaf(d, d, acc);
            if (rem > 1) { d = p.y - __logf(a.y); acc = fmaf(d, d, acc); }
            if (rem > 2) { d = p.z - __logf(a.z); acc = fmaf(d, d, acc); }
        }
    }

    // Deterministic block reduction: warp shuffle then smem tree.
    __shared__ float warp_sums[BLOCK / 32];
    #pragma unroll
    for (int off = 16; off > 0; off >>= 1)
        acc += __shfl_down_sync(0xFFFFFFFFu, acc, off);
    if ((threadIdx.x & 31) == 0)
        warp_sums[threadIdx.x >> 5] = acc;
    __syncthreads();

    if (threadIdx.x < 32) {
        float v = (threadIdx.x < BLOCK / 32) ? warp_sums[threadIdx.x] : 0.0f;
        #pragma unroll
        for (int off = 16; off > 0; off >>= 1)
            v += __shfl_down_sync(0xFFFFFFFFu, v, off);
        if (threadIdx.x == 0)
            g_row_mse[row] = v / (float)L;
    }
}

// ---------------------------------------------------------------------------
// Kernel 2: single block reduces the B per-row values to the batch mean.
// Fixed tree order -> deterministic.
// ---------------------------------------------------------------------------
template <int BLOCK>
__global__ void final_mean_kernel(float* __restrict__ out, int B) {
    float acc = 0.0f;
    for (int i = threadIdx.x; i < B; i += BLOCK)
        acc += g_row_mse[i];

    __shared__ float warp_sums[BLOCK / 32];
    #pragma unroll
    for (int off = 16; off > 0; off >>= 1)
        acc += __shfl_down_sync(0xFFFFFFFFu, acc, off);
    if ((threadIdx.x & 31) == 0)
        warp_sums[threadIdx.x >> 5] = acc;
    __syncthreads();

    if (threadIdx.x < 32) {
        float v = (threadIdx.x < BLOCK / 32) ? warp_sums[threadIdx.x] : 0.0f;
        #pragma unroll
        for (int off = 16; off > 0; off >>= 1)
            v += __shfl_down_sync(0xFFFFFFFFu, v, off);
        if (threadIdx.x == 0)
            out[0] = v / (float)B;
    }
}

extern "C" void kernel_launch(void* const* d_in, const int* in_sizes, int n_in,
                              void* d_out, int out_size) {
    const float* pred  = (const float*)d_in[0];
    const float* align = (const float*)d_in[1];
    const int*   lens  = (const int*)d_in[2];
    float* out = (float*)d_out;

    const int B = in_sizes[2];
    const int T = in_sizes[0] / B;

    constexpr int BLOCK = 256;
    row_mse_kernel<BLOCK><<<B, BLOCK>>>(pred, align, lens, T);
    final_mean_kernel<1024><<<1, 1024>>>(out, B);
}

// round 2
// speedup vs baseline: 1.1376x; 1.1376x over previous
#include <cuda_runtime.h>
#include <cuda_bf16.h>

#define MAX_B 8192
__device__ float g_row_mse[MAX_B];
__device__ int   g_done_ctr = 0;

// ---------------------------------------------------------------------------
// Fused kernel: one CTA per row computes the masked per-row MSE over the
// valid prefix only (ceil(L/4) float4 chunks -> ~half the HBM traffic of a
// full-row read since E[L] ~ T/2). The last CTA to finish performs the batch
// mean over g_row_mse in a FIXED deterministic order and writes d_out[0],
// then resets the counter so the kernel is graph-replay-safe.
// ---------------------------------------------------------------------------
template <int BLOCK>
__global__ void dploss_fused_kernel(const float* __restrict__ pred,
                                    const float* __restrict__ align,
                                    const int* __restrict__ lens,
                                    float* __restrict__ out,
                                    int T, int B) {
    const int row = blockIdx.x;
    const int L = lens[row];
    const size_t base = (size_t)row * (size_t)T;
    const float4* __restrict__ p4 = reinterpret_cast<const float4*>(pred + base);
    const float4* __restrict__ a4 = reinterpret_cast<const float4*>(align + base);

    const int nfull = L >> 2;   // float4 chunks with all 4 lanes valid

    float acc = 0.0f;

    // Hot path: branch-free over fully-valid chunks.
    for (int i = threadIdx.x; i < nfull; i += BLOCK) {
        float4 p = p4[i];
        float4 a = a4[i];
        float d0 = p.x - __logf(a.x);
        float d1 = p.y - __logf(a.y);
        float d2 = p.z - __logf(a.z);
        float d3 = p.w - __logf(a.w);
        acc = fmaf(d0, d0, acc);
        acc = fmaf(d1, d1, acc);
        acc = fmaf(d2, d2, acc);
        acc = fmaf(d3, d3, acc);
    }

    // At most one partial tail chunk (1..3 valid lanes); thread 0 handles it.
    // Safe to read p4[nfull]: L&3 != 0 implies L < T, and T is a multiple of 4.
    if ((L & 3) && threadIdx.x == 0) {
        float4 p = p4[nfull];
        float4 a = a4[nfull];
        int rem = L & 3;
        float d;
        d = p.x - __logf(a.x); acc = fmaf(d, d, acc);
        if (rem > 1) { d = p.y - __logf(a.y); acc = fmaf(d, d, acc); }
        if (rem > 2) { d = p.z - __logf(a.z); acc = fmaf(d, d, acc); }
    }

    // Deterministic block reduction: warp shuffle, then smem tree.
    __shared__ float warp_sums[BLOCK / 32];
    #pragma unroll
    for (int off = 16; off > 0; off >>= 1)
        acc += __shfl_down_sync(0xFFFFFFFFu, acc, off);
    if ((threadIdx.x & 31) == 0)
        warp_sums[threadIdx.x >> 5] = acc;
    __syncthreads();

    __shared__ bool s_is_last;
    if (threadIdx.x == 0) {
        float v = 0.0f;
        #pragma unroll
        for (int w = 0; w < BLOCK / 32; w++)
            v += warp_sums[w];
        g_row_mse[row] = v / (float)L;
        __threadfence();                         // publish before counting done
        int old = atomicAdd(&g_done_ctr, 1);
        s_is_last = (old == B - 1);
    }
    __syncthreads();

    if (s_is_last) {
        // Last CTA: deterministic batch mean over all row MSEs (hot in L2).
        float v = 0.0f;
        for (int i = threadIdx.x; i < B; i += BLOCK)
            v += g_row_mse[i];

        #pragma unroll
        for (int off = 16; off > 0; off >>= 1)
            v += __shfl_down_sync(0xFFFFFFFFu, v, off);
        if ((threadIdx.x & 31) == 0)
            warp_sums[threadIdx.x >> 5] = v;
        __syncthreads();

        if (threadIdx.x == 0) {
            float t = 0.0f;
            #pragma unroll
            for (int w = 0; w < BLOCK / 32; w++)
                t += warp_sums[w];
            out[0] = t / (float)B;
            g_done_ctr = 0;                      // reset for next graph replay
        }
    }
}

extern "C" void kernel_launch(void* const* d_in, const int* in_sizes, int n_in,
                              void* d_out, int out_size) {
    const float* pred  = (const float*)d_in[0];
    const float* align = (const float*)d_in[1];
    const int*   lens  = (const int*)d_in[2];
    float* out = (float*)d_out;

    const int B = in_sizes[2];
    const int T = in_sizes[0] / B;

    constexpr int BLOCK = 128;
    dploss_fused_kernel<BLOCK><<<B, BLOCK>>>(pred, align, lens, out, T, B);
}

// round 3
// speedup vs baseline: 1.1604x; 1.0201x over previous
#include <cuda_runtime.h>
#include <cuda_bf16.h>

#define MAX_GRID 4096
__device__ float g_partials[MAX_GRID];
__device__ int   g_done_ctr = 0;

// ---------------------------------------------------------------------------
// Flat weighted reduction:
//   loss = (1/B) * sum_{row} sum_{t < L[row]} (pred - log(align))^2 / L[row]
// The 1/L weight is applied per-chunk, so the entire [B, T/4] chunk space is
// one flat reduction -> perfect load balance across SMs regardless of the
// per-row length distribution. Invalid chunks are skipped (zero traffic).
// Unroll x4 with independent accumulators -> 8 outstanding LDG.128 / thread.
// ---------------------------------------------------------------------------
template <int BLOCK>
__global__ void dploss_flat_kernel(const float* __restrict__ pred,
                                   const float* __restrict__ align,
                                   const int* __restrict__ lens,
                                   float* __restrict__ out,
                                   int C,        // chunks per row = T/4
                                   int lc,       // log2(C) if power of two, else -1
                                   int nChunks,  // B * C
                                   int B) {
    const float4* __restrict__ p4 = reinterpret_cast<const float4*>(pred);
    const float4* __restrict__ a4 = reinterpret_cast<const float4*>(align);

    const int stride = gridDim.x * BLOCK;
    int g = blockIdx.x * BLOCK + threadIdx.x;

    float acc0 = 0.0f, acc1 = 0.0f, acc2 = 0.0f, acc3 = 0.0f;

    // Main unrolled-by-4 loop: 4 independent chunk slots per iteration.
    for (; g + 3 * stride < nChunks; g += 4 * stride) {
        int gg0 = g, gg1 = g + stride, gg2 = g + 2 * stride, gg3 = g + 3 * stride;
        int r0, c0, r1, c1, r2, c2, r3, c3;
        if (lc >= 0) {
            r0 = gg0 >> lc; c0 = gg0 & (C - 1);
            r1 = gg1 >> lc; c1 = gg1 & (C - 1);
            r2 = gg2 >> lc; c2 = gg2 & (C - 1);
            r3 = gg3 >> lc; c3 = gg3 & (C - 1);
        } else {
            r0 = gg0 / C; c0 = gg0 - r0 * C;
            r1 = gg1 / C; c1 = gg1 - r1 * C;
            r2 = gg2 / C; c2 = gg2 - r2 * C;
            r3 = gg3 / C; c3 = gg3 - r3 * C;
        }
        int L0 = __ldg(lens + r0);
        int L1 = __ldg(lens + r1);
        int L2 = __ldg(lens + r2);
        int L3 = __ldg(lens + r3);

        int rem0 = L0 - (c0 << 2);
        int rem1 = L1 - (c1 << 2);
        int rem2 = L2 - (c2 << 2);
        int rem3 = L3 - (c3 << 2);

        // Issue all loads for valid slots up front (max MLP).
        float4 p0, a0, p1, a1, p2, a2, p3, a3;
        bool v0 = rem0 > 0, v1 = rem1 > 0, v2 = rem2 > 0, v3 = rem3 > 0;
        if (v0) { p0 = p4[gg0]; a0 = a4[gg0]; }
        if (v1) { p1 = p4[gg1]; a1 = a4[gg1]; }
        if (v2) { p2 = p4[gg2]; a2 = a4[gg2]; }
        if (v3) { p3 = p4[gg3]; a3 = a4[gg3]; }

        if (v0) {
            float d0 = p0.x - __logf(a0.x);
            float s = d0 * d0;
            if (rem0 > 1) { float d = p0.y - __logf(a0.y); s = fmaf(d, d, s); }
            if (rem0 > 2) { float d = p0.z - __logf(a0.z); s = fmaf(d, d, s); }
            if (rem0 > 3) { float d = p0.w - __logf(a0.w); s = fmaf(d, d, s); }
            acc0 = fmaf(s, __fdividef(1.0f, (float)L0), acc0);
        }
        if (v1) {
            float d0 = p1.x - __logf(a1.x);
            float s = d0 * d0;
            if (rem1 > 1) { float d = p1.y - __logf(a1.y); s = fmaf(d, d, s); }
            if (rem1 > 2) { float d = p1.z - __logf(a1.z); s = fmaf(d, d, s); }
            if (rem1 > 3) { float d = p1.w - __logf(a1.w); s = fmaf(d, d, s); }
            acc1 = fmaf(s, __fdividef(1.0f, (float)L1), acc1);
        }
        if (v2) {
            float d0 = p2.x - __logf(a2.x);
            float s = d0 * d0;
            if (rem2 > 1) { float d = p2.y - __logf(a2.y); s = fmaf(d, d, s); }
            if (rem2 > 2) { float d = p2.z - __logf(a2.z); s = fmaf(d, d, s); }
            if (rem2 > 3) { float d = p2.w - __logf(a2.w); s = fmaf(d, d, s); }
            acc2 = fmaf(s, __fdividef(1.0f, (float)L2), acc2);
        }
        if (v3) {
            float d0 = p3.x - __logf(a3.x);
            float s = d0 * d0;
            if (rem3 > 1) { float d = p3.y - __logf(a3.y); s = fmaf(d, d, s); }
            if (rem3 > 2) { float d = p3.z - __logf(a3.z); s = fmaf(d, d, s); }
            if (rem3 > 3) { float d = p3.w - __logf(a3.w); s = fmaf(d, d, s); }
            acc3 = fmaf(s, __fdividef(1.0f, (float)L3), acc3);
        }
    }

    // Remainder loop.
    for (; g < nChunks; g += stride) {
        int r, c;
        if (lc >= 0) { r = g >> lc; c = g & (C - 1); }
        else         { r = g / C;   c = g - r * C; }
        int L = __ldg(lens + r);
        int rem = L - (c << 2);
        if (rem > 0) {
            float4 p = p4[g];
            float4 a = a4[g];
            float d0 = p.x - __logf(a.x);
            float s = d0 * d0;
            if (rem > 1) { float d = p.y - __logf(a.y); s = fmaf(d, d, s); }
            if (rem > 2) { float d = p.z - __logf(a.z); s = fmaf(d, d, s); }
            if (rem > 3) { float d = p.w - __logf(a.w); s = fmaf(d, d, s); }
            acc0 = fmaf(s, __fdividef(1.0f, (float)L), acc0);
        }
    }

    float acc = (acc0 + acc1) + (acc2 + acc3);

    // Deterministic block reduction.
    __shared__ float warp_sums[BLOCK / 32];
    #pragma unroll
    for (int off = 16; off > 0; off >>= 1)
        acc += __shfl_down_sync(0xFFFFFFFFu, acc, off);
    if ((threadIdx.x & 31) == 0)
        warp_sums[threadIdx.x >> 5] = acc;
    __syncthreads();

    __shared__ bool s_is_last;
    if (threadIdx.x == 0) {
        float v = 0.0f;
        #pragma unroll
        for (int w = 0; w < BLOCK / 32; w++)
            v += warp_sums[w];
        g_partials[blockIdx.x] = v;
        __threadfence();
        int old = atomicAdd(&g_done_ctr, 1);
        s_is_last = (old == (int)gridDim.x - 1);
    }
    __syncthreads();

    if (s_is_last) {
        // Last CTA: deterministic reduce of per-CTA partials (hot in L2).
        float v = 0.0f;
        for (int i = threadIdx.x; i < (int)gridDim.x; i += BLOCK)
            v += g_partials[i];
        #pragma unroll
        for (int off = 16; off > 0; off >>= 1)
            v += __shfl_down_sync(0xFFFFFFFFu, v, off);
        if ((threadIdx.x & 31) == 0)
            warp_sums[threadIdx.x >> 5] = v;
        __syncthreads();
        if (threadIdx.x == 0) {
            float t = 0.0f;
            #pragma unroll
            for (int w = 0; w < BLOCK / 32; w++)
                t += warp_sums[w];
            out[0] = t / (float)B;
            g_done_ctr = 0;     // reset for next graph replay
        }
    }
}

extern "C" void kernel_launch(void* const* d_in, const int* in_sizes, int n_in,
                              void* d_out, int out_size) {
    const float* pred  = (const float*)d_in[0];
    const float* align = (const float*)d_in[1];
    const int*   lens  = (const int*)d_in[2];
    float* out = (float*)d_out;

    const int B = in_sizes[2];
    const int T = in_sizes[0] / B;
    const int C = T >> 2;                 // float4 chunks per row
    const int nChunks = B * C;

    int lc = -1;
    if ((C & (C - 1)) == 0) {             // power of two -> shift/mask path
        lc = 0;
        while ((1 << lc) != C) lc++;
    }

    constexpr int BLOCK = 256;
    // ~8 chunk-slots per thread; single resident wave on 148 SMs.
    int grid = (nChunks + BLOCK * 8 - 1) / (BLOCK * 8);
    if (grid > MAX_GRID) grid = MAX_GRID;
    if (grid < 1) grid = 1;

    dploss_flat_kernel<BLOCK><<<grid, BLOCK>>>(pred, align, lens, out,
                                               C, lc, nChunks, B);
}

// round 4
// speedup vs baseline: 1.1633x; 1.0025x over previous
#include <cuda_runtime.h>
#include <cuda_bf16.h>

#define MAX_CTAS 8192
__device__ float g_partials[MAX_CTAS];
__device__ int   g_done_ctr = 0;

// ---------------------------------------------------------------------------
// Warp-tile kernel. Each warp owns one tile of 128 float4-chunks (512 elems)
// inside a single row. The row length is loaded ONCE per warp, so all 8 data
// loads (4 groups x {pred,align}) are predicated purely on registers and get
// front-batched by ptxas (high MLP). Lanes are consecutive chunks -> fully
// coalesced. Tiles past the valid prefix exit after one L1-hit lens load.
//   loss = (1/B) * sum_row (1/L) * sum_{t<L} (pred - log(align))^2
// ---------------------------------------------------------------------------
template <int BLOCK>
__global__ void dploss_warptile_kernel(const float* __restrict__ pred,
                                       const float* __restrict__ align,
                                       const int* __restrict__ lens,
                                       float* __restrict__ out,
                                       int C,           // float4 chunks per row
                                       int tilesPerRow, // ceil(C / 128)
                                       int nTiles,      // B * tilesPerRow
                                       int B) {
    const float4* __restrict__ p4 = reinterpret_cast<const float4*>(pred);
    const float4* __restrict__ a4 = reinterpret_cast<const float4*>(align);

    const int lane = threadIdx.x & 31;
    const int warpGlobal = (blockIdx.x * BLOCK + threadIdx.x) >> 5;
    const int warpStride = (gridDim.x * BLOCK) >> 5;

    float acc = 0.0f;

    for (int t = warpGlobal; t < nTiles; t += warpStride) {
        const int row = t / tilesPerRow;
        const int tix = t - row * tilesPerRow;
        const int L = __ldg(lens + row);         // ONE dependent load per tile
        const int c0 = tix << 7;                 // first chunk of this tile
        const int V = (L + 3) >> 2;              // valid chunks in this row
        if (c0 >= V) continue;                   // fully-invalid tile: no traffic

        const size_t rowBase = (size_t)row * (size_t)C;
        float s = 0.0f;

        #pragma unroll
        for (int i = 0; i < 4; i++) {
            const int c = c0 + (i << 5) + lane;  // this lane's chunk
            const int rem = L - (c << 2);        // valid elems in chunk (<=0 none)
            if (rem > 0) {
                float4 p = p4[rowBase + c];
                float4 a = a4[rowBase + c];
                float d0 = p.x - __logf(a.x);
                float ss = d0 * d0;
                if (rem > 1) { float d = p.y - __logf(a.y); ss = fmaf(d, d, ss); }
                if (rem > 2) { float d = p.z - __logf(a.z); ss = fmaf(d, d, ss); }
                if (rem > 3) { float d = p.w - __logf(a.w); ss = fmaf(d, d, ss); }
                s += ss;
            }
        }
        // Per-row weight applied once per tile.
        acc = fmaf(s, __fdividef(1.0f, (float)L), acc);
    }

    // Deterministic block reduction: warp shuffle, then fixed-order smem sum.
    __shared__ float warp_sums[BLOCK / 32];
    #pragma unroll
    for (int off = 16; off > 0; off >>= 1)
        acc += __shfl_down_sync(0xFFFFFFFFu, acc, off);
    if (lane == 0)
        warp_sums[threadIdx.x >> 5] = acc;
    __syncthreads();

    __shared__ bool s_is_last;
    if (threadIdx.x == 0) {
        float v = 0.0f;
        #pragma unroll
        for (int w = 0; w < BLOCK / 32; w++)
            v += warp_sums[w];
        g_partials[blockIdx.x] = v;
        __threadfence();
        int old = atomicAdd(&g_done_ctr, 1);
        s_is_last = (old == (int)gridDim.x - 1);
    }
    __syncthreads();

    if (s_is_last) {
        float v = 0.0f;
        for (int i = threadIdx.x; i < (int)gridDim.x; i += BLOCK)
            v += g_partials[i];
        #pragma unroll
        for (int off = 16; off > 0; off >>= 1)
            v += __shfl_down_sync(0xFFFFFFFFu, v, off);
        if ((threadIdx.x & 31) == 0)
            warp_sums[threadIdx.x >> 5] = v;
        __syncthreads();
        if (threadIdx.x == 0) {
            float tt = 0.0f;
            #pragma unroll
            for (int w = 0; w < BLOCK / 32; w++)
                tt += warp_sums[w];
            out[0] = tt / (float)B;
            g_done_ctr = 0;   // reset for next graph replay
        }
    }
}

extern "C" void kernel_launch(void* const* d_in, const int* in_sizes, int n_in,
                              void* d_out, int out_size) {
    const float* pred  = (const float*)d_in[0];
    const float* align = (const float*)d_in[1];
    const int*   lens  = (const int*)d_in[2];
    float* out = (float*)d_out;

    const int B = in_sizes[2];
    const int T = in_sizes[0] / B;
    const int C = T >> 2;                      // float4 chunks per row
    const int tilesPerRow = (C + 127) >> 7;    // 128-chunk tiles
    const int nTiles = B * tilesPerRow;

    constexpr int BLOCK = 256;                 // 8 warps = 8 tiles per CTA
    int grid = (nTiles * 32 + BLOCK - 1) / BLOCK;
    if (grid > MAX_CTAS) grid = MAX_CTAS;      // then warps grid-stride tiles
    if (grid < 1) grid = 1;

    dploss_warptile_kernel<BLOCK><<<grid, BLOCK>>>(pred, align, lens, out,
                                                   C, tilesPerRow, nTiles, B);
}

// round 5
// speedup vs baseline: 1.3821x; 1.1881x over previous
#include <cuda_runtime.h>
#include <cuda_bf16.h>

#define MAX_B 8192
__device__ float g_row_mse[MAX_B];
__device__ int   g_done_ctr = 0;

// ---------------------------------------------------------------------------
// Warp-per-row kernel. Each warp owns one full row: loads lens ONCE, then
// streams the valid prefix with a x4-chunk batched loop (8 independent
// LDG.128 per iteration, zero per-element predicates in the full region).
// 512 CTAs x 256 threads = 4096 warps = one warp per row, single launch wave.
//   loss = (1/B) * sum_row (1/L) * sum_{t<L} (pred - log(align))^2
// Per-row results are statically owned -> deterministic; last CTA reduces
// g_row_mse in fixed order.
// ---------------------------------------------------------------------------
template <int BLOCK>
__global__ void dploss_warprow_kernel(const float* __restrict__ pred,
                                      const float* __restrict__ align,
                                      const int* __restrict__ lens,
                                      float* __restrict__ out,
                                      int C,   // float4 chunks per row (T/4)
                                      int B) {
    const int lane = threadIdx.x & 31;
    const int warpsPerGrid = (gridDim.x * BLOCK) >> 5;
    const int warpId = (blockIdx.x * BLOCK + threadIdx.x) >> 5;

    for (int row = warpId; row < B; row += warpsPerGrid) {
        const int L = __ldg(lens + row);          // one lens load per row
        const int nfull = L >> 2;                 // fully-valid chunks
        const size_t base = (size_t)row * (size_t)C;
        const float4* __restrict__ p4 = reinterpret_cast<const float4*>(pred) + base;
        const float4* __restrict__ a4 = reinterpret_cast<const float4*>(align) + base;

        float s0 = 0.0f, s1 = 0.0f, s2 = 0.0f, s3 = 0.0f;

        int c = lane;
        // Hot loop: 4 full chunks per iteration, 8 independent LDG.128 batched.
        for (; c + 96 < nfull; c += 128) {
            float4 pA = p4[c];
            float4 aA = a4[c];
            float4 pB = p4[c + 32];
            float4 aB = a4[c + 32];
            float4 pC = p4[c + 64];
            float4 aC = a4[c + 64];
            float4 pD = p4[c + 96];
            float4 aD = a4[c + 96];

            float d;
            d = pA.x - __logf(aA.x); s0 = fmaf(d, d, s0);
            d = pA.y - __logf(aA.y); s0 = fmaf(d, d, s0);
            d = pA.z - __logf(aA.z); s0 = fmaf(d, d, s0);
            d = pA.w - __logf(aA.w); s0 = fmaf(d, d, s0);
            d = pB.x - __logf(aB.x); s1 = fmaf(d, d, s1);
            d = pB.y - __logf(aB.y); s1 = fmaf(d, d, s1);
            d = pB.z - __logf(aB.z); s1 = fmaf(d, d, s1);
            d = pB.w - __logf(aB.w); s1 = fmaf(d, d, s1);
            d = pC.x - __logf(aC.x); s2 = fmaf(d, d, s2);
            d = pC.y - __logf(aC.y); s2 = fmaf(d, d, s2);
            d = pC.z - __logf(aC.z); s2 = fmaf(d, d, s2);
            d = pC.w - __logf(aC.w); s2 = fmaf(d, d, s2);
            d = pD.x - __logf(aD.x); s3 = fmaf(d, d, s3);
            d = pD.y - __logf(aD.y); s3 = fmaf(d, d, s3);
            d = pD.z - __logf(aD.z); s3 = fmaf(d, d, s3);
            d = pD.w - __logf(aD.w); s3 = fmaf(d, d, s3);
        }
        // Remaining full chunks.
        for (; c < nfull; c += 32) {
            float4 p = p4[c];
            float4 a = a4[c];
            float d;
            d = p.x - __logf(a.x); s0 = fmaf(d, d, s0);
            d = p.y - __logf(a.y); s1 = fmaf(d, d, s1);
            d = p.z - __logf(a.z); s2 = fmaf(d, d, s2);
            d = p.w - __logf(a.w); s3 = fmaf(d, d, s3);
        }
        // Partial tail chunk (1..3 valid elems); owned by one lane.
        // Safe read: L&3 != 0 implies L < T, so chunk nfull < C.
        if ((L & 3) && lane == (nfull & 31)) {
            float4 p = p4[nfull];
            float4 a = a4[nfull];
            int rem = L & 3;
            float d;
            d = p.x - __logf(a.x); s0 = fmaf(d, d, s0);
            if (rem > 1) { d = p.y - __logf(a.y); s1 = fmaf(d, d, s1); }
            if (rem > 2) { d = p.z - __logf(a.z); s2 = fmaf(d, d, s2); }
        }

        float s = (s0 + s1) + (s2 + s3);
        // Warp reduction (fixed order -> deterministic).
        #pragma unroll
        for (int off = 16; off > 0; off >>= 1)
            s += __shfl_down_sync(0xFFFFFFFFu, s, off);
        if (lane == 0)
            g_row_mse[row] = s * __frcp_rn((float)L);
    }

    // Signal completion; last CTA reduces all rows in fixed order.
    __syncthreads();
    __shared__ bool s_is_last;
    if (threadIdx.x == 0) {
        __threadfence();
        int old = atomicAdd(&g_done_ctr, 1);
        s_is_last = (old == (int)gridDim.x - 1);
    }
    __syncthreads();

    if (s_is_last) {
        float v = 0.0f;
        for (int i = threadIdx.x; i < B; i += BLOCK)   // fixed strided order
            v += g_row_mse[i];
        __shared__ float warp_sums[BLOCK / 32];
        #pragma unroll
        for (int off = 16; off > 0; off >>= 1)
            v += __shfl_down_sync(0xFFFFFFFFu, v, off);
        if ((threadIdx.x & 31) == 0)
            warp_sums[threadIdx.x >> 5] = v;
        __syncthreads();
        if (threadIdx.x == 0) {
            float t = 0.0f;
            #pragma unroll
            for (int w = 0; w < BLOCK / 32; w++)
                t += warp_sums[w];
            out[0] = t / (float)B;
            g_done_ctr = 0;   // reset for next graph replay
        }
    }
}

extern "C" void kernel_launch(void* const* d_in, const int* in_sizes, int n_in,
                              void* d_out, int out_size) {
    const float* pred  = (const float*)d_in[0];
    const float* align = (const float*)d_in[1];
    const int*   lens  = (const int*)d_in[2];
    float* out = (float*)d_out;

    const int B = in_sizes[2];
    const int T = in_sizes[0] / B;
    const int C = T >> 2;

    constexpr int BLOCK = 256;                     // 8 warps per CTA
    int grid = (B + (BLOCK / 32) - 1) / (BLOCK / 32);  // one warp per row
    if (grid < 1) grid = 1;
    if (grid > 4096) grid = 4096;                  // warps then grid-stride rows

    dploss_warprow_kernel<BLOCK><<<grid, BLOCK>>>(pred, align, lens, out, C, B);
}